// round 2
// baseline (speedup 1.0000x reference)
#include <cuda_runtime.h>
#include <math.h>
#include <stdint.h>
#include <stddef.h>

// Problem constants
constexpr int NV = 32000;   // vocab
constexpr int NE = 1024;    // embed dim
constexpr int NH = 1024;    // hidden
constexpr int NB = 64;      // batch
constexpr int NT = 64;      // decode steps
constexpr int NS = 128;     // encoder length
constexpr int NG = 3 * NH;  // 3072 gates

// ---------------------------------------------------------------------------
// Scratch (static device globals; no allocation allowed)
// ---------------------------------------------------------------------------
__device__ float g_kproj[(size_t)NB * NS * NH];   // enc_Y @ Wk^T + bk
__device__ float g_emb[(size_t)NT * NB * NE];     // gathered embeddings, time-major
__device__ float g_h[2 * NB * NH];                // current hidden state (2 layers)
__device__ float g_qp[4 * NB * NH];               // q split-K partials
__device__ float g_ctx[NB * NH];                  // attention context
__device__ float g_gi0a[NB * NG];
__device__ float g_gi0b[NB * NG];
__device__ float g_gh0[NB * NG];
__device__ float g_gi1[NB * NG];
__device__ float g_gh1[NB * NG];
__device__ float g_ys[(size_t)NT * NB * NH];      // layer-1 outputs, [T,B,H]

// ---------------------------------------------------------------------------
// Generic fp32 NT GEMM:  C[m,n] = sum_k A[m,k] * W[n,k]   (A:[M,K], W:[N,K])
// Tile 64x64, BK=16, 128 threads, each thread 4x8 outputs.
// ---------------------------------------------------------------------------
struct GemmOp {
    const float* A;
    const float* W;
    float*       C;
    int lda, ldw, ldc, K;
};
struct GemmOps4 { GemmOp op[4]; };

__device__ __forceinline__ void gemm_tile_core(const float* __restrict__ A, int lda,
                                               const float* __restrict__ W, int ldw,
                                               int K, float acc[4][8]) {
    __shared__ float As[16 * 64];
    __shared__ float Ws[16 * 64];
    const int tid = threadIdx.x;
    const int tx  = tid & 7;          // 0..7  (n groups)
    const int ty  = tid >> 3;         // 0..15 (m groups)
    const int r0  = tid >> 2;         // 0..31 load row
    const int c0  = (tid & 3) * 4;    // 0,4,8,12 load k-col

    for (int kt = 0; kt < K; kt += 16) {
        float4 a0 = *(const float4*)(A + (size_t)r0 * lda + kt + c0);
        float4 a1 = *(const float4*)(A + (size_t)(r0 + 32) * lda + kt + c0);
        float4 w0 = *(const float4*)(W + (size_t)r0 * ldw + kt + c0);
        float4 w1 = *(const float4*)(W + (size_t)(r0 + 32) * ldw + kt + c0);

        As[(c0 + 0) * 64 + r0] = a0.x;  As[(c0 + 1) * 64 + r0] = a0.y;
        As[(c0 + 2) * 64 + r0] = a0.z;  As[(c0 + 3) * 64 + r0] = a0.w;
        As[(c0 + 0) * 64 + r0 + 32] = a1.x;  As[(c0 + 1) * 64 + r0 + 32] = a1.y;
        As[(c0 + 2) * 64 + r0 + 32] = a1.z;  As[(c0 + 3) * 64 + r0 + 32] = a1.w;
        Ws[(c0 + 0) * 64 + r0] = w0.x;  Ws[(c0 + 1) * 64 + r0] = w0.y;
        Ws[(c0 + 2) * 64 + r0] = w0.z;  Ws[(c0 + 3) * 64 + r0] = w0.w;
        Ws[(c0 + 0) * 64 + r0 + 32] = w1.x;  Ws[(c0 + 1) * 64 + r0 + 32] = w1.y;
        Ws[(c0 + 2) * 64 + r0 + 32] = w1.z;  Ws[(c0 + 3) * 64 + r0 + 32] = w1.w;
        __syncthreads();

#pragma unroll
        for (int k = 0; k < 16; ++k) {
            const float4 av = *(const float4*)&As[k * 64 + ty * 4];
            const float4 b0 = *(const float4*)&Ws[k * 64 + tx * 4];
            const float4 b1 = *(const float4*)&Ws[k * 64 + 32 + tx * 4];
            float a_[4] = {av.x, av.y, av.z, av.w};
            float b_[8] = {b0.x, b0.y, b0.z, b0.w, b1.x, b1.y, b1.z, b1.w};
#pragma unroll
            for (int i = 0; i < 4; ++i)
#pragma unroll
                for (int j = 0; j < 8; ++j)
                    acc[i][j] = fmaf(a_[i], b_[j], acc[i][j]);
        }
        __syncthreads();
    }
}

// MODE 0: C[m*ldc + n].  MODE 1: projection epilogue -> out[b][t][n], m = t*NB + b.
template <int MODE>
__global__ void sgemm_single(GemmOp op, const float* __restrict__ bias) {
    const int bn = blockIdx.x, bm = blockIdx.y;
    float acc[4][8];
#pragma unroll
    for (int i = 0; i < 4; ++i)
#pragma unroll
        for (int j = 0; j < 8; ++j) acc[i][j] = 0.0f;

    gemm_tile_core(op.A + (size_t)bm * 64 * op.lda, op.lda,
                   op.W + (size_t)bn * 64 * op.ldw, op.ldw, op.K, acc);

    const int tx = threadIdx.x & 7, ty = threadIdx.x >> 3;
#pragma unroll
    for (int i = 0; i < 4; ++i) {
        const int m = bm * 64 + ty * 4 + i;
#pragma unroll
        for (int j = 0; j < 8; ++j) {
            const int nl = (j < 4) ? (tx * 4 + j) : (32 + tx * 4 + (j - 4));
            const int n  = bn * 64 + nl;
            float v = acc[i][j] + (bias ? bias[n] : 0.0f);
            if (MODE == 0) {
                op.C[(size_t)m * op.ldc + n] = v;
            } else {
                const int b = m & (NB - 1);
                const int t = m >> 6;
                op.C[((size_t)b * NT + t) * NV + n] = v;
            }
        }
    }
}

// Multiple independent same-shape GEMMs in one launch (fills the chip for M=64).
__global__ void sgemm_multi(GemmOps4 ops) {
    const GemmOp op = ops.op[blockIdx.z];
    const int bn = blockIdx.x;
    float acc[4][8];
#pragma unroll
    for (int i = 0; i < 4; ++i)
#pragma unroll
        for (int j = 0; j < 8; ++j) acc[i][j] = 0.0f;

    gemm_tile_core(op.A, op.lda, op.W + (size_t)bn * 64 * op.ldw, op.ldw, op.K, acc);

    const int tx = threadIdx.x & 7, ty = threadIdx.x >> 3;
#pragma unroll
    for (int i = 0; i < 4; ++i) {
        const int m = ty * 4 + i;
#pragma unroll
        for (int j = 0; j < 8; ++j) {
            const int nl = (j < 4) ? (tx * 4 + j) : (32 + tx * 4 + (j - 4));
            op.C[(size_t)m * op.ldc + bn * 64 + nl] = acc[i][j];
        }
    }
}

// ---------------------------------------------------------------------------
// Attention: scores_s = wv . tanh(q + kproj[b,s]) + bv ; softmax ; ctx = attn @ enc_Y
// ---------------------------------------------------------------------------
__device__ __forceinline__ float fast_tanh(float x) {
    float y;
    asm("tanh.approx.f32 %0, %1;" : "=f"(y) : "f"(x));
    return y;
}

__global__ void attn_kernel(const float* __restrict__ qp, const float* __restrict__ bq,
                            const float* __restrict__ kproj,
                            const float* __restrict__ wv, const float* __restrict__ bv,
                            const float* __restrict__ encY, float* __restrict__ ctx) {
    const int b = blockIdx.x, tid = threadIdx.x;
    __shared__ float qs[NH];
    __shared__ float wvs[NH];
    __shared__ float sc[NS];

    for (int h = tid; h < NH; h += 256) {
        qs[h] = qp[(size_t)b * NH + h]
              + qp[(size_t)NB * NH + b * NH + h]
              + qp[(size_t)2 * NB * NH + b * NH + h]
              + qp[(size_t)3 * NB * NH + b * NH + h] + bq[h];
        wvs[h] = wv[h];
    }
    __syncthreads();

    const int warp = tid >> 5, lane = tid & 31;
    const float* kp = kproj + (size_t)b * NS * NH;
    for (int s = warp; s < NS; s += 8) {
        const float* kr = kp + (size_t)s * NH;
        float acc = 0.0f;
        for (int h = lane; h < NH; h += 32)
            acc += wvs[h] * fast_tanh(qs[h] + kr[h]);
#pragma unroll
        for (int o = 16; o; o >>= 1) acc += __shfl_xor_sync(0xffffffffu, acc, o);
        if (lane == 0) sc[s] = acc + bv[0];
    }
    __syncthreads();

    if (warp == 0) {
        float v0 = sc[lane], v1 = sc[lane + 32], v2 = sc[lane + 64], v3 = sc[lane + 96];
        float m = fmaxf(fmaxf(v0, v1), fmaxf(v2, v3));
#pragma unroll
        for (int o = 16; o; o >>= 1) m = fmaxf(m, __shfl_xor_sync(0xffffffffu, m, o));
        float e0 = __expf(v0 - m), e1 = __expf(v1 - m), e2 = __expf(v2 - m), e3 = __expf(v3 - m);
        float ss = e0 + e1 + e2 + e3;
#pragma unroll
        for (int o = 16; o; o >>= 1) ss += __shfl_xor_sync(0xffffffffu, ss, o);
        float inv = 1.0f / ss;
        sc[lane] = e0 * inv; sc[lane + 32] = e1 * inv;
        sc[lane + 64] = e2 * inv; sc[lane + 96] = e3 * inv;
    }
    __syncthreads();

    const float* ey = encY + (size_t)b * NS * NH;
    for (int h = tid; h < NH; h += 256) {
        float acc = 0.0f;
#pragma unroll 8
        for (int s = 0; s < NS; ++s) acc += sc[s] * ey[(size_t)s * NH + h];
        ctx[(size_t)b * NH + h] = acc;
    }
}

// ---------------------------------------------------------------------------
// GRU cell: reduces split-K partials + biases, applies gates, updates h.
// ---------------------------------------------------------------------------
__global__ void gru_cell_kernel(const float* __restrict__ giA, const float* __restrict__ giB,
                                const float* __restrict__ gh,
                                const float* __restrict__ bih, const float* __restrict__ bhh,
                                float* __restrict__ hbuf, float* __restrict__ ysout) {
    const int idx = blockIdx.x * blockDim.x + threadIdx.x;
    if (idx >= NB * NH) return;
    const int b = idx >> 10;
    const int h = idx & (NH - 1);
    const size_t base = (size_t)b * NG;

    float ir = giA[base + h], iz = giA[base + NH + h], in_ = giA[base + 2 * NH + h];
    if (giB) {
        ir  += giB[base + h];
        iz  += giB[base + NH + h];
        in_ += giB[base + 2 * NH + h];
    }
    ir += bih[h]; iz += bih[NH + h]; in_ += bih[2 * NH + h];

    const float hr = gh[base + h] + bhh[h];
    const float hz = gh[base + NH + h] + bhh[NH + h];
    const float hn = gh[base + 2 * NH + h] + bhh[2 * NH + h];

    const float hp = hbuf[idx];
    const float r = 1.0f / (1.0f + __expf(-(ir + hr)));
    const float z = 1.0f / (1.0f + __expf(-(iz + hz)));
    const float n = tanhf(in_ + r * hn);
    const float out = (1.0f - z) * n + z * hp;
    hbuf[idx] = out;
    if (ysout) ysout[idx] = out;
}

// ---------------------------------------------------------------------------
// Embedding gather into time-major buffer: emb[t][b][:] = table[X[b][t]]
// ---------------------------------------------------------------------------
__global__ void embed_kernel(const int* __restrict__ X, const float* __restrict__ table,
                             float* __restrict__ emb) {
    const size_t i = (size_t)blockIdx.x * 256 + threadIdx.x;
    const size_t total = (size_t)NT * NB * (NE / 4);
    if (i >= total) return;
    const int e4 = (int)(i % (NE / 4));
    const int tb = (int)(i / (NE / 4));
    const int t = tb / NB, b = tb % NB;
    const int tok = X[b * NT + t];
    ((float4*)emb)[i] = ((const float4*)(table + (size_t)tok * NE))[e4];
}

// ---------------------------------------------------------------------------
// In-place log-softmax over V per (b,t) row.
// ---------------------------------------------------------------------------
__global__ void logsoftmax_kernel(float* __restrict__ out) {
    float* p = out + (size_t)blockIdx.x * NV;
    const int tid = threadIdx.x;
    __shared__ float red[32];

    float m = -1e30f;
    for (int v = tid; v < NV; v += 256) m = fmaxf(m, p[v]);
#pragma unroll
    for (int o = 16; o; o >>= 1) m = fmaxf(m, __shfl_xor_sync(0xffffffffu, m, o));
    if ((tid & 31) == 0) red[tid >> 5] = m;
    __syncthreads();
    if (tid < 32) {
        float x = (tid < 8) ? red[tid] : -1e30f;
#pragma unroll
        for (int o = 4; o; o >>= 1) x = fmaxf(x, __shfl_xor_sync(0xffffffffu, x, o));
        if (tid == 0) red[0] = x;
    }
    __syncthreads();
    m = red[0];
    __syncthreads();

    float s = 0.0f;
    for (int v = tid; v < NV; v += 256) s += __expf(p[v] - m);
#pragma unroll
    for (int o = 16; o; o >>= 1) s += __shfl_xor_sync(0xffffffffu, s, o);
    if ((tid & 31) == 0) red[tid >> 5] = s;
    __syncthreads();
    if (tid < 32) {
        float x = (tid < 8) ? red[tid] : 0.0f;
#pragma unroll
        for (int o = 4; o; o >>= 1) x += __shfl_xor_sync(0xffffffffu, x, o);
        if (tid == 0) red[0] = x;
    }
    __syncthreads();
    const float lse = m + logf(red[0]);
    for (int v = tid; v < NV; v += 256) p[v] -= lse;
}

// ---------------------------------------------------------------------------
// Host orchestration
// ---------------------------------------------------------------------------
extern "C" void kernel_launch(void* const* d_in, const int* in_sizes, int n_in,
                              void* d_out, int out_size) {
    (void)in_sizes; (void)n_in; (void)out_size;
    const int*   X     = (const int*)d_in[0];
    const float* encY  = (const float*)d_in[1];
    const float* h0    = (const float*)d_in[2];
    const float* table = (const float*)d_in[3];
    const float* Wq    = (const float*)d_in[4];
    const float* bq    = (const float*)d_in[5];
    const float* Wk    = (const float*)d_in[6];
    const float* bk    = (const float*)d_in[7];
    const float* wv    = (const float*)d_in[8];
    const float* bv    = (const float*)d_in[9];
    const float* Wih0  = (const float*)d_in[10];
    const float* Whh0  = (const float*)d_in[11];
    const float* bih0  = (const float*)d_in[12];
    const float* bhh0  = (const float*)d_in[13];
    const float* Wih1  = (const float*)d_in[14];
    const float* Whh1  = (const float*)d_in[15];
    const float* bih1  = (const float*)d_in[16];
    const float* bhh1  = (const float*)d_in[17];
    const float* Wout  = (const float*)d_in[18];
    const float* bout  = (const float*)d_in[19];
    float* out = (float*)d_out;

    void* p;
    cudaGetSymbolAddress(&p, g_kproj); float* kproj = (float*)p;
    cudaGetSymbolAddress(&p, g_emb);   float* emb   = (float*)p;
    cudaGetSymbolAddress(&p, g_h);     float* hbuf  = (float*)p;
    cudaGetSymbolAddress(&p, g_qp);    float* qp    = (float*)p;
    cudaGetSymbolAddress(&p, g_ctx);   float* ctx   = (float*)p;
    cudaGetSymbolAddress(&p, g_gi0a);  float* gi0a  = (float*)p;
    cudaGetSymbolAddress(&p, g_gi0b);  float* gi0b  = (float*)p;
    cudaGetSymbolAddress(&p, g_gh0);   float* gh0   = (float*)p;
    cudaGetSymbolAddress(&p, g_gi1);   float* gi1   = (float*)p;
    cudaGetSymbolAddress(&p, g_gh1);   float* gh1   = (float*)p;
    cudaGetSymbolAddress(&p, g_ys);    float* ysb   = (float*)p;

    // init hidden state
    cudaMemcpyAsync(hbuf, h0, (size_t)2 * NB * NH * sizeof(float),
                    cudaMemcpyDeviceToDevice, 0);

    // gather embeddings (time-major)
    embed_kernel<<<(unsigned)(((size_t)NT * NB * (NE / 4) + 255) / 256), 256>>>(X, table, emb);

    // kproj = enc_Y @ Wk^T + bk   (M = B*S)
    {
        GemmOp op;
        op.A = encY; op.lda = NH;
        op.W = Wk;   op.ldw = NH;
        op.C = kproj; op.ldc = NH; op.K = NH;
        sgemm_single<0><<<dim3(NH / 64, (NB * NS) / 64), 128>>>(op, bk);
    }

    for (int t = 0; t < NT; ++t) {
        // q = h1 @ Wq^T  (split-K x4 partials; bias folded into attn kernel)
        GemmOps4 qops;
        for (int sp = 0; sp < 4; ++sp) {
            GemmOp& o = qops.op[sp];
            o.A = hbuf + NB * NH + sp * 256; o.lda = NH;
            o.W = Wq + sp * 256;             o.ldw = NH;
            o.C = qp + (size_t)sp * NB * NH; o.ldc = NH; o.K = 256;
        }
        sgemm_multi<<<dim3(NH / 64, 1, 4), 128>>>(qops);

        attn_kernel<<<NB, 256>>>(qp, bq, kproj, wv, bv, encY, ctx);

        // layer-0 gates: gi split over [ctx | emb] columns of Wih0, plus gh
        GemmOps4 g0;
        g0.op[0].A = ctx;                       g0.op[0].lda = NH;
        g0.op[0].W = Wih0;                      g0.op[0].ldw = NH + NE;
        g0.op[0].C = gi0a;                      g0.op[0].ldc = NG;  g0.op[0].K = NH;
        g0.op[1].A = emb + (size_t)t * NB * NE; g0.op[1].lda = NE;
        g0.op[1].W = Wih0 + NH;                 g0.op[1].ldw = NH + NE;
        g0.op[1].C = gi0b;                      g0.op[1].ldc = NG;  g0.op[1].K = NE;
        g0.op[2].A = hbuf;                      g0.op[2].lda = NH;
        g0.op[2].W = Whh0;                      g0.op[2].ldw = NH;
        g0.op[2].C = gh0;                       g0.op[2].ldc = NG;  g0.op[2].K = NH;
        g0.op[3] = g0.op[2];
        sgemm_multi<<<dim3(NG / 64, 1, 3), 128>>>(g0);

        gru_cell_kernel<<<(NB * NH) / 256, 256>>>(gi0a, gi0b, gh0, bih0, bhh0,
                                                  hbuf, nullptr);

        // layer-1 gates
        GemmOps4 g1;
        g1.op[0].A = hbuf;           g1.op[0].lda = NH;
        g1.op[0].W = Wih1;           g1.op[0].ldw = NH;
        g1.op[0].C = gi1;            g1.op[0].ldc = NG; g1.op[0].K = NH;
        g1.op[1].A = hbuf + NB * NH; g1.op[1].lda = NH;
        g1.op[1].W = Whh1;           g1.op[1].ldw = NH;
        g1.op[1].C = gh1;            g1.op[1].ldc = NG; g1.op[1].K = NH;
        g1.op[2] = g1.op[1];
        g1.op[3] = g1.op[1];
        sgemm_multi<<<dim3(NG / 64, 1, 2), 128>>>(g1);

        gru_cell_kernel<<<(NB * NH) / 256, 256>>>(gi1, nullptr, gh1, bih1, bhh1,
                                                  hbuf + NB * NH,
                                                  ysb + (size_t)t * NB * NH);
    }

    // logits = ys @ Wout^T + bout, written permuted into out[b][t][v]
    {
        GemmOp op;
        op.A = ysb;  op.lda = NH;
        op.W = Wout; op.ldw = NH;
        op.C = out;  op.ldc = NV; op.K = NH;
        sgemm_single<1><<<dim3(NV / 64, (NT * NB) / 64), 128>>>(op, bout);
    }

    // in-place log-softmax over vocab
    logsoftmax_kernel<<<NB * NT, 256>>>(out);
}

// round 6
// speedup vs baseline: 2.0891x; 2.0891x over previous
#include <cuda_runtime.h>
#include <math.h>
#include <stdint.h>
#include <stddef.h>

// Problem constants
constexpr int NV = 32000;   // vocab
constexpr int NE = 1024;    // embed dim
constexpr int NH = 1024;    // hidden
constexpr int NB = 64;      // batch
constexpr int NT = 64;      // decode steps
constexpr int NS = 128;     // encoder length
constexpr int NG = 3 * NH;  // 3072 gates

// ---------------------------------------------------------------------------
// Scratch (static device globals; no allocation allowed)
// ---------------------------------------------------------------------------
__device__ float g_kproj[(size_t)NB * NS * NH];   // enc_Y @ Wk^T + bk
__device__ float g_emb[(size_t)NT * NB * NE];     // gathered embeddings, time-major
__device__ float g_h[2 * NB * NH];                // current hidden state (2 layers)
__device__ float g_qp[4 * NB * NH];               // q split-K partials
__device__ float g_scores[NB * NS];               // attention scores
__device__ float g_ctx[NB * NH];                  // attention context
__device__ float g_gi0a[NB * NG];
__device__ float g_gi0b[NB * NG];
__device__ float g_gh0[NB * NG];
__device__ float g_gi1[NB * NG];
__device__ float g_gh1[NB * NG];
__device__ float g_ys[(size_t)NT * NB * NH];      // layer-1 outputs, [T,B,H]

struct GemmOp {
    const float* A;
    const float* W;
    float*       C;
    int lda, ldw, ldc, K;
};
struct GemmOps4 { GemmOp op[4]; };

// ---------------------------------------------------------------------------
// tf32 tensor-core GEMM:  C[m,n] = sum_k A[m,k] * W[n,k]
// mma.sync.aligned.m16n8k8.row.col.f32.tf32.tf32.f32, fp32 accumulate.
// Inputs stay fp32 in memory; rounded to tf32 at the smem stage.
// ---------------------------------------------------------------------------
__device__ __forceinline__ uint32_t f2tf32(float x) {
    uint32_t r;
    asm("cvt.rna.tf32.f32 %0, %1;" : "=r"(r) : "f"(x));
    return r;
}

__device__ __forceinline__ void mma_tf32(float c[4], const uint32_t a[4],
                                         const uint32_t b[2]) {
    asm volatile(
        "mma.sync.aligned.m16n8k8.row.col.f32.tf32.tf32.f32 "
        "{%0,%1,%2,%3}, {%4,%5,%6,%7}, {%8,%9}, {%0,%1,%2,%3};"
        : "+f"(c[0]), "+f"(c[1]), "+f"(c[2]), "+f"(c[3])
        : "r"(a[0]), "r"(a[1]), "r"(a[2]), "r"(a[3]), "r"(b[0]), "r"(b[1]));
}

// Core tile body. 256 threads = 8 warps, warp grid WGM x WGN (WGM*WGN == 8).
// Block tile: BM = WGM*MT*16, BN = WGN*NTT*8.  BK = 16, smem row stride 20.
// MODE 0: C[m*ldc + n] (+bias).  MODE 1: out[b][t][n] with b=m&63, t=m>>6 (+bias).
template <int WGM, int WGN, int MT, int NTT, int MODE>
__device__ __forceinline__ void tf32_gemm_body(const GemmOp op,
                                               const float* __restrict__ bias,
                                               int bm, int bn) {
    constexpr int BM = WGM * MT * 16;
    constexpr int BN = WGN * NTT * 8;
    constexpr int PAD = 20;
    __shared__ uint32_t As[BM * PAD];
    __shared__ uint32_t Ws[BN * PAD];

    const int tid  = threadIdx.x;
    const int warp = tid >> 5, lane = tid & 31;
    const int wm = warp / WGN, wn = warp % WGN;
    const int m_off = wm * MT * 16;
    const int n_off = wn * NTT * 8;
    const int lg = lane >> 2;     // 0..7
    const int lk = lane & 3;      // 0..3

    const float* Ab = op.A + (size_t)bm * BM * op.lda;
    const float* Wb = op.W + (size_t)bn * BN * op.ldw;

    float acc[MT][NTT][4];
#pragma unroll
    for (int i = 0; i < MT; ++i)
#pragma unroll
        for (int j = 0; j < NTT; ++j)
#pragma unroll
            for (int c = 0; c < 4; ++c) acc[i][j][c] = 0.0f;

    const int r0 = tid >> 2;
    const int c0 = (tid & 3) * 4;

    for (int kt = 0; kt < op.K; kt += 16) {
#pragma unroll
        for (int i = 0; i < BM / 64; ++i) {
            const int r = r0 + 64 * i;
            float4 v = *(const float4*)(Ab + (size_t)r * op.lda + kt + c0);
            As[r * PAD + c0 + 0] = f2tf32(v.x);
            As[r * PAD + c0 + 1] = f2tf32(v.y);
            As[r * PAD + c0 + 2] = f2tf32(v.z);
            As[r * PAD + c0 + 3] = f2tf32(v.w);
        }
#pragma unroll
        for (int i = 0; i < BN / 64; ++i) {
            const int r = r0 + 64 * i;
            float4 v = *(const float4*)(Wb + (size_t)r * op.ldw + kt + c0);
            Ws[r * PAD + c0 + 0] = f2tf32(v.x);
            Ws[r * PAD + c0 + 1] = f2tf32(v.y);
            Ws[r * PAD + c0 + 2] = f2tf32(v.z);
            Ws[r * PAD + c0 + 3] = f2tf32(v.w);
        }
        __syncthreads();

#pragma unroll
        for (int ks = 0; ks < 2; ++ks) {
            const int k0 = ks * 8;
            uint32_t af[MT][4], bf[NTT][2];
#pragma unroll
            for (int mt = 0; mt < MT; ++mt) {
                const int r = m_off + mt * 16 + lg;
                af[mt][0] = As[r * PAD + k0 + lk];
                af[mt][1] = As[(r + 8) * PAD + k0 + lk];
                af[mt][2] = As[r * PAD + k0 + lk + 4];
                af[mt][3] = As[(r + 8) * PAD + k0 + lk + 4];
            }
#pragma unroll
            for (int nt = 0; nt < NTT; ++nt) {
                const int n = n_off + nt * 8 + lg;
                bf[nt][0] = Ws[n * PAD + k0 + lk];
                bf[nt][1] = Ws[n * PAD + k0 + lk + 4];
            }
#pragma unroll
            for (int mt = 0; mt < MT; ++mt)
#pragma unroll
                for (int nt = 0; nt < NTT; ++nt)
                    mma_tf32(acc[mt][nt], af[mt], bf[nt]);
        }
        __syncthreads();
    }

    // Epilogue
#pragma unroll
    for (int mt = 0; mt < MT; ++mt) {
#pragma unroll
        for (int nt = 0; nt < NTT; ++nt) {
            const int m = bm * BM + m_off + mt * 16 + lg;
            const int n = bn * BN + n_off + nt * 8 + 2 * lk;
            float b0 = bias ? bias[n] : 0.0f;
            float b1 = bias ? bias[n + 1] : 0.0f;
            float2 v0 = {acc[mt][nt][0] + b0, acc[mt][nt][1] + b1};
            float2 v1 = {acc[mt][nt][2] + b0, acc[mt][nt][3] + b1};
            if (MODE == 0) {
                *(float2*)(op.C + (size_t)m * op.ldc + n) = v0;
                *(float2*)(op.C + (size_t)(m + 8) * op.ldc + n) = v1;
            } else {
                const int b_0 = m & (NB - 1), t_0 = m >> 6;
                const int b_1 = (m + 8) & (NB - 1), t_1 = (m + 8) >> 6;
                *(float2*)(op.C + ((size_t)b_0 * NT + t_0) * NV + n) = v0;
                *(float2*)(op.C + ((size_t)b_1 * NT + t_1) * NV + n) = v1;
            }
        }
    }
}

// Large-tile single GEMM: 128x128 block tile.
template <int MODE>
__global__ __launch_bounds__(256) void tf32_gemm_single(GemmOp op,
                                                        const float* __restrict__ bias) {
    tf32_gemm_body<2, 4, 4, 4, MODE>(op, bias, blockIdx.x, blockIdx.y);
}

// Small-M multi GEMM: 64x64 block tile, M == 64, op selected by blockIdx.z.
__global__ __launch_bounds__(256) void tf32_gemm_multi(GemmOps4 ops) {
    tf32_gemm_body<4, 2, 1, 4, 0>(ops.op[blockIdx.z], nullptr, 0, blockIdx.x);
}

// ---------------------------------------------------------------------------
// Attention, split for parallelism.
// ---------------------------------------------------------------------------
__device__ __forceinline__ float fast_tanh(float x) {
    float y;
    asm("tanh.approx.f32 %0, %1;" : "=f"(y) : "f"(x));
    return y;
}

// scores[b][s] = wv . tanh(q_b + kproj[b,s]) + bv,  q_b = sum of 4 partials + bq
// grid (NB, NS/16), 256 threads; each warp computes 2 scores.
__global__ void scores_kernel(const float* __restrict__ qp, const float* __restrict__ bq,
                              const float* __restrict__ kproj,
                              const float* __restrict__ wv, const float* __restrict__ bv,
                              float* __restrict__ scores) {
    const int b = blockIdx.x, sb = blockIdx.y, tid = threadIdx.x;
    __shared__ float qs[NH];
    __shared__ float wvs[NH];

    for (int h = tid; h < NH; h += 256) {
        qs[h] = qp[(size_t)b * NH + h]
              + qp[(size_t)NB * NH + b * NH + h]
              + qp[(size_t)2 * NB * NH + b * NH + h]
              + qp[(size_t)3 * NB * NH + b * NH + h] + bq[h];
        wvs[h] = wv[h];
    }
    __syncthreads();

    const int warp = tid >> 5, lane = tid & 31;
    const int s0 = sb * 16 + warp * 2;
    const float* k0 = kproj + ((size_t)b * NS + s0) * NH;
    float acc0 = 0.0f, acc1 = 0.0f;
    for (int h = lane; h < NH; h += 32) {
        const float q = qs[h], w = wvs[h];
        acc0 += w * fast_tanh(q + k0[h]);
        acc1 += w * fast_tanh(q + k0[NH + h]);
    }
#pragma unroll
    for (int o = 16; o; o >>= 1) {
        acc0 += __shfl_xor_sync(0xffffffffu, acc0, o);
        acc1 += __shfl_xor_sync(0xffffffffu, acc1, o);
    }
    if (lane == 0) {
        scores[b * NS + s0]     = acc0 + bv[0];
        scores[b * NS + s0 + 1] = acc1 + bv[0];
    }
}

// softmax over scores (redundant per block, cheap) + ctx chunk.
// grid (NB, NH/128), 128 threads; thread t handles column h = hb*128 + t.
__global__ void softmax_ctx_kernel(const float* __restrict__ scores,
                                   const float* __restrict__ encY,
                                   float* __restrict__ ctx) {
    const int b = blockIdx.x, hb = blockIdx.y, tid = threadIdx.x;
    __shared__ float at[NS];
    __shared__ float redm[4];
    __shared__ float reds[4];
    const int warp = tid >> 5, lane = tid & 31;

    const float sc = scores[b * NS + tid];
    float m = sc;
#pragma unroll
    for (int o = 16; o; o >>= 1) m = fmaxf(m, __shfl_xor_sync(0xffffffffu, m, o));
    if (lane == 0) redm[warp] = m;
    __syncthreads();
    m = fmaxf(fmaxf(redm[0], redm[1]), fmaxf(redm[2], redm[3]));

    const float e = __expf(sc - m);
    float s = e;
#pragma unroll
    for (int o = 16; o; o >>= 1) s += __shfl_xor_sync(0xffffffffu, s, o);
    if (lane == 0) reds[warp] = s;
    __syncthreads();
    s = reds[0] + reds[1] + reds[2] + reds[3];
    at[tid] = e / s;
    __syncthreads();

    const int h = hb * 128 + tid;
    const float* ey = encY + (size_t)b * NS * NH + h;
    float acc = 0.0f;
#pragma unroll 4
    for (int si = 0; si < NS; ++si) acc += at[si] * ey[(size_t)si * NH];
    ctx[(size_t)b * NH + h] = acc;
}

// ---------------------------------------------------------------------------
// GRU cell
// ---------------------------------------------------------------------------
__global__ void gru_cell_kernel(const float* __restrict__ giA, const float* __restrict__ giB,
                                const float* __restrict__ gh,
                                const float* __restrict__ bih, const float* __restrict__ bhh,
                                float* __restrict__ hbuf, float* __restrict__ ysout) {
    const int idx = blockIdx.x * blockDim.x + threadIdx.x;
    if (idx >= NB * NH) return;
    const int b = idx >> 10;
    const int h = idx & (NH - 1);
    const size_t base = (size_t)b * NG;

    float ir = giA[base + h], iz = giA[base + NH + h], in_ = giA[base + 2 * NH + h];
    if (giB) {
        ir  += giB[base + h];
        iz  += giB[base + NH + h];
        in_ += giB[base + 2 * NH + h];
    }
    ir += bih[h]; iz += bih[NH + h]; in_ += bih[2 * NH + h];

    const float hr = gh[base + h] + bhh[h];
    const float hz = gh[base + NH + h] + bhh[NH + h];
    const float hn = gh[base + 2 * NH + h] + bhh[2 * NH + h];

    const float hp = hbuf[idx];
    const float r = 1.0f / (1.0f + __expf(-(ir + hr)));
    const float z = 1.0f / (1.0f + __expf(-(iz + hz)));
    const float n = tanhf(in_ + r * hn);
    const float out = (1.0f - z) * n + z * hp;
    hbuf[idx] = out;
    if (ysout) ysout[idx] = out;
}

// ---------------------------------------------------------------------------
// Embedding gather: emb[t][b][:] = table[X[b][t]]
// ---------------------------------------------------------------------------
__global__ void embed_kernel(const int* __restrict__ X, const float* __restrict__ table,
                             float* __restrict__ emb) {
    const size_t i = (size_t)blockIdx.x * 256 + threadIdx.x;
    const size_t total = (size_t)NT * NB * (NE / 4);
    if (i >= total) return;
    const int e4 = (int)(i % (NE / 4));
    const int tb = (int)(i / (NE / 4));
    const int t = tb / NB, b = tb % NB;
    const int tok = X[b * NT + t];
    ((float4*)emb)[i] = ((const float4*)(table + (size_t)tok * NE))[e4];
}

// ---------------------------------------------------------------------------
// In-place log-softmax over V per (b,t) row.
// ---------------------------------------------------------------------------
__global__ void logsoftmax_kernel(float* __restrict__ out) {
    float* p = out + (size_t)blockIdx.x * NV;
    const int tid = threadIdx.x;
    __shared__ float red[32];

    float m = -1e30f;
    for (int v = tid; v < NV; v += 256) m = fmaxf(m, p[v]);
#pragma unroll
    for (int o = 16; o; o >>= 1) m = fmaxf(m, __shfl_xor_sync(0xffffffffu, m, o));
    if ((tid & 31) == 0) red[tid >> 5] = m;
    __syncthreads();
    if (tid < 32) {
        float x = (tid < 8) ? red[tid] : -1e30f;
#pragma unroll
        for (int o = 4; o; o >>= 1) x = fmaxf(x, __shfl_xor_sync(0xffffffffu, x, o));
        if (tid == 0) red[0] = x;
    }
    __syncthreads();
    m = red[0];
    __syncthreads();

    float s = 0.0f;
    for (int v = tid; v < NV; v += 256) s += __expf(p[v] - m);
#pragma unroll
    for (int o = 16; o; o >>= 1) s += __shfl_xor_sync(0xffffffffu, s, o);
    if ((tid & 31) == 0) red[tid >> 5] = s;
    __syncthreads();
    if (tid < 32) {
        float x = (tid < 8) ? red[tid] : 0.0f;
#pragma unroll
        for (int o = 4; o; o >>= 1) x += __shfl_xor_sync(0xffffffffu, x, o);
        if (tid == 0) red[0] = x;
    }
    __syncthreads();
    const float lse = m + logf(red[0]);
    for (int v = tid; v < NV; v += 256) p[v] -= lse;
}

// ---------------------------------------------------------------------------
// Host orchestration
// ---------------------------------------------------------------------------
extern "C" void kernel_launch(void* const* d_in, const int* in_sizes, int n_in,
                              void* d_out, int out_size) {
    (void)in_sizes; (void)n_in; (void)out_size;
    const int*   X     = (const int*)d_in[0];
    const float* encY  = (const float*)d_in[1];
    const float* h0    = (const float*)d_in[2];
    const float* table = (const float*)d_in[3];
    const float* Wq    = (const float*)d_in[4];
    const float* bq    = (const float*)d_in[5];
    const float* Wk    = (const float*)d_in[6];
    const float* bk    = (const float*)d_in[7];
    const float* wv    = (const float*)d_in[8];
    const float* bv    = (const float*)d_in[9];
    const float* Wih0  = (const float*)d_in[10];
    const float* Whh0  = (const float*)d_in[11];
    const float* bih0  = (const float*)d_in[12];
    const float* bhh0  = (const float*)d_in[13];
    const float* Wih1  = (const float*)d_in[14];
    const float* Whh1  = (const float*)d_in[15];
    const float* bih1  = (const float*)d_in[16];
    const float* bhh1  = (const float*)d_in[17];
    const float* Wout  = (const float*)d_in[18];
    const float* bout  = (const float*)d_in[19];
    float* out = (float*)d_out;

    void* p;
    cudaGetSymbolAddress(&p, g_kproj);  float* kproj  = (float*)p;
    cudaGetSymbolAddress(&p, g_emb);    float* emb    = (float*)p;
    cudaGetSymbolAddress(&p, g_h);      float* hbuf   = (float*)p;
    cudaGetSymbolAddress(&p, g_qp);     float* qp     = (float*)p;
    cudaGetSymbolAddress(&p, g_scores); float* scores = (float*)p;
    cudaGetSymbolAddress(&p, g_ctx);    float* ctx    = (float*)p;
    cudaGetSymbolAddress(&p, g_gi0a);   float* gi0a   = (float*)p;
    cudaGetSymbolAddress(&p, g_gi0b);   float* gi0b   = (float*)p;
    cudaGetSymbolAddress(&p, g_gh0);    float* gh0    = (float*)p;
    cudaGetSymbolAddress(&p, g_gi1);    float* gi1    = (float*)p;
    cudaGetSymbolAddress(&p, g_gh1);    float* gh1    = (float*)p;
    cudaGetSymbolAddress(&p, g_ys);     float* ysb    = (float*)p;

    cudaMemcpyAsync(hbuf, h0, (size_t)2 * NB * NH * sizeof(float),
                    cudaMemcpyDeviceToDevice, 0);

    embed_kernel<<<(unsigned)(((size_t)NT * NB * (NE / 4) + 255) / 256), 256>>>(X, table, emb);

    // kproj = enc_Y @ Wk^T + bk   (M = B*S = 8192, N = 1024, K = 1024)
    {
        GemmOp op;
        op.A = encY;  op.lda = NH;
        op.W = Wk;    op.ldw = NH;
        op.C = kproj; op.ldc = NH; op.K = NH;
        tf32_gemm_single<0><<<dim3((NB * NS) / 128, NH / 128), 256>>>(op, bk);
    }

    for (int t = 0; t < NT; ++t) {
        // q = h1 @ Wq^T  (split-K x4 partials; bias folded into scores kernel)
        GemmOps4 qops;
        for (int sp = 0; sp < 4; ++sp) {
            GemmOp& o = qops.op[sp];
            o.A = hbuf + NB * NH + sp * 256; o.lda = NH;
            o.W = Wq + sp * 256;             o.ldw = NH;
            o.C = qp + (size_t)sp * NB * NH; o.ldc = NH; o.K = 256;
        }
        tf32_gemm_multi<<<dim3(NH / 64, 1, 4), 256>>>(qops);

        scores_kernel<<<dim3(NB, NS / 16), 256>>>(qp, bq, kproj, wv, bv, scores);
        softmax_ctx_kernel<<<dim3(NB, NH / 128), 128>>>(scores, encY, ctx);

        // layer-0 gates
        GemmOps4 g0;
        g0.op[0].A = ctx;                       g0.op[0].lda = NH;
        g0.op[0].W = Wih0;                      g0.op[0].ldw = NH + NE;
        g0.op[0].C = gi0a;                      g0.op[0].ldc = NG;  g0.op[0].K = NH;
        g0.op[1].A = emb + (size_t)t * NB * NE; g0.op[1].lda = NE;
        g0.op[1].W = Wih0 + NH;                 g0.op[1].ldw = NH + NE;
        g0.op[1].C = gi0b;                      g0.op[1].ldc = NG;  g0.op[1].K = NE;
        g0.op[2].A = hbuf;                      g0.op[2].lda = NH;
        g0.op[2].W = Whh0;                      g0.op[2].ldw = NH;
        g0.op[2].C = gh0;                       g0.op[2].ldc = NG;  g0.op[2].K = NH;
        g0.op[3] = g0.op[2];
        tf32_gemm_multi<<<dim3(NG / 64, 1, 3), 256>>>(g0);

        gru_cell_kernel<<<(NB * NH) / 256, 256>>>(gi0a, gi0b, gh0, bih0, bhh0,
                                                  hbuf, nullptr);

        // layer-1 gates
        GemmOps4 g1;
        g1.op[0].A = hbuf;           g1.op[0].lda = NH;
        g1.op[0].W = Wih1;           g1.op[0].ldw = NH;
        g1.op[0].C = gi1;            g1.op[0].ldc = NG; g1.op[0].K = NH;
        g1.op[1].A = hbuf + NB * NH; g1.op[1].lda = NH;
        g1.op[1].W = Whh1;           g1.op[1].ldw = NH;
        g1.op[1].C = gh1;            g1.op[1].ldc = NG; g1.op[1].K = NH;
        g1.op[2] = g1.op[1];
        g1.op[3] = g1.op[1];
        tf32_gemm_multi<<<dim3(NG / 64, 1, 2), 256>>>(g1);

        gru_cell_kernel<<<(NB * NH) / 256, 256>>>(gi1, nullptr, gh1, bih1, bhh1,
                                                  hbuf + NB * NH,
                                                  ysb + (size_t)t * NB * NH);
    }

    // logits = ys @ Wout^T + bout, permuted epilogue into out[b][t][v]
    {
        GemmOp op;
        op.A = ysb;  op.lda = NH;
        op.W = Wout; op.ldw = NH;
        op.C = out;  op.ldc = NV; op.K = NH;
        tf32_gemm_single<1><<<dim3((NT * NB) / 128, NV / 128), 256>>>(op, bout);
    }

    logsoftmax_kernel<<<NB * NT, 256>>>(out);
}